// round 14
// baseline (speedup 1.0000x reference)
#include <cuda_runtime.h>
#include <cuda_fp16.h>
#include <math.h>
#include <stdint.h>

#define TOKENS 1024
#define HD 2880
#define E_NUM 16
#define I_DIM 2880
#define GU (2*I_DIM)
#define TOPK 4
#define NPAIR (TOKENS*TOPK)
#define ALPHA 1.702f
#define LIMIT 7.0f
#define BK 32                    // fp32 K elems per stage
#define KIT 90                   // HD/BK == I_DIM/BK
#define ROWB 80                  // smem row pitch: 64B data + 16B pad (conflict-free ldmatrix)
#define NT 96                    // CTA N-tile: divides 5760 (60) and 2880 (30) exactly

#define REG_A (128 * ROWB)       // 10240  (A: 128 rows x 32 fp16)
#define REG_B (NT * ROWB)        // 7680   (B: 96 rows x 32 fp16)
#define OFF_A 0
#define OFF_B REG_A
#define BUFB (REG_A + REG_B)     // 17920
#define SMEM_TOT (2 * BUFB)      // 35840 per CTA (2 CTAs/SM -> 71.7KB/SM)

// ---------------- scratch ----------------
__device__ float g_act[NPAIR * I_DIM];
__device__ int   g_cnt[E_NUM];
__device__ int   g_list[E_NUM * TOKENS];
__device__ int   g_pe[NPAIR];
__device__ float g_pp[NPAIR];

// ---------------- helpers ----------------
__device__ __forceinline__ uint32_t smem_u32(const void* p) {
    uint32_t a;
    asm("{ .reg .u64 t; cvta.to.shared.u64 t, %1; cvt.u32.u64 %0, t; }" : "=r"(a) : "l"(p));
    return a;
}
#define LDSM4(r, addr) \
    asm volatile("ldmatrix.sync.aligned.m8n8.x4.shared.b16 {%0,%1,%2,%3}, [%4];" \
        : "=r"((r)[0]), "=r"((r)[1]), "=r"((r)[2]), "=r"((r)[3]) : "r"(addr))
#define MMA16816(d, a, b0, b1) \
    asm volatile("mma.sync.aligned.m16n8k16.row.col.f32.f16.f16.f32 " \
        "{%0,%1,%2,%3}, {%4,%5,%6,%7}, {%8,%9}, {%0,%1,%2,%3};" \
        : "+f"((d)[0]), "+f"((d)[1]), "+f"((d)[2]), "+f"((d)[3]) \
        : "r"((a)[0]), "r"((a)[1]), "r"((a)[2]), "r"((a)[3]), "r"(b0), "r"(b1))

// convert 8 float4 (32 fp32, one full row) -> 32 fp16 (64B) and store at byte offset off
__device__ __forceinline__ void store_row_h(const float4* v, unsigned char* sm, uint32_t off) {
    uint32_t w[16];
    #pragma unroll
    for (int q = 0; q < 8; q++) {
        __half2 h0 = __floats2half2_rn(v[q].x, v[q].y);
        __half2 h1 = __floats2half2_rn(v[q].z, v[q].w);
        w[2 * q]     = *(uint32_t*)&h0;
        w[2 * q + 1] = *(uint32_t*)&h1;
    }
    *(uint4*)(sm + off)      = make_uint4(w[0],  w[1],  w[2],  w[3]);
    *(uint4*)(sm + off + 16) = make_uint4(w[4],  w[5],  w[6],  w[7]);
    *(uint4*)(sm + off + 32) = make_uint4(w[8],  w[9],  w[10], w[11]);
    *(uint4*)(sm + off + 48) = make_uint4(w[12], w[13], w[14], w[15]);
}
__device__ __forceinline__ void load_row8(const float* __restrict__ src, float4* v) {
    const float4* s4 = (const float4*)src;
    #pragma unroll
    for (int q = 0; q < 8; q++) v[q] = s4[q];
}
__device__ __forceinline__ void stage_row_h(const float* __restrict__ src,
                                            unsigned char* sm, uint32_t off) {
    float4 v[8];
    load_row8(src, v);
    store_row_h(v, sm, off);
}

// ---------------- small kernels ----------------
__global__ void k_init() {
    if (threadIdx.x < E_NUM) g_cnt[threadIdx.x] = 0;
}

__global__ void k_zero_out(float* __restrict__ out) {
    const int total4 = TOKENS * HD / 4;
    for (int i = blockIdx.x * blockDim.x + threadIdx.x; i < total4; i += gridDim.x * blockDim.x)
        ((float4*)out)[i] = make_float4(0.f, 0.f, 0.f, 0.f);
}

__global__ void k_router(const float* __restrict__ flat,
                         const float* __restrict__ rw,
                         const float* __restrict__ rb) {
    int t = blockIdx.x, tid = threadIdx.x;
    const float* x = flat + (size_t)t * HD;
    float part[E_NUM];
    #pragma unroll
    for (int e = 0; e < E_NUM; e++) part[e] = 0.f;
    for (int h = tid; h < HD; h += 128) {
        float xv = x[h];
        #pragma unroll
        for (int e = 0; e < E_NUM; e++) part[e] += xv * rw[e * HD + h];
    }
    __shared__ float sm[E_NUM][128];
    #pragma unroll
    for (int e = 0; e < E_NUM; e++) sm[e][tid] = part[e];
    __syncthreads();
    if (tid < E_NUM) {
        float s = 0.f;
        for (int j = 0; j < 128; j++) s += sm[tid][j];
        sm[tid][0] = s + rb[tid];
    }
    __syncthreads();
    if (tid == 0) {
        float v[E_NUM];
        #pragma unroll
        for (int e = 0; e < E_NUM; e++) v[e] = sm[e][0];
        int idx[TOPK]; float val[TOPK];
        #pragma unroll
        for (int k = 0; k < TOPK; k++) {
            int bi = 0; float bv = -1e30f;
            #pragma unroll
            for (int e = 0; e < E_NUM; e++)
                if (v[e] > bv) { bv = v[e]; bi = e; }
            idx[k] = bi; val[k] = bv; v[bi] = -1e30f;
        }
        float m = val[0], s = 0.f, p[TOPK];
        #pragma unroll
        for (int k = 0; k < TOPK; k++) { p[k] = __expf(val[k] - m); s += p[k]; }
        float inv = 1.f / s;
        #pragma unroll
        for (int k = 0; k < TOPK; k++) {
            int pid = t * TOPK + k;
            g_pe[pid] = idx[k];
            g_pp[pid] = p[k] * inv;
            int slot = atomicAdd(&g_cnt[idx[k]], 1);
            g_list[idx[k] * TOKENS + slot] = pid;
        }
    }
}

// Half MMA body: one ks slice. Warp tile 64x48: mt=4 (16-row), p=3 (16-col), nt=p*2+half.
#define MMA_HALF(u0, cb, aoffs, boffs, acc, ks) do { \
    const uint32_t kb = (uint32_t)(ks) * 32u; \
    uint32_t aH[4][4]; \
    _Pragma("unroll") \
    for (int mt = 0; mt < 4; mt++) \
        LDSM4(aH[mt], (u0) + (cb) + OFF_A + (aoffs) + (uint32_t)mt * 16 * ROWB + kb); \
    _Pragma("unroll") \
    for (int p = 0; p < 3; p++) { \
        uint32_t bH[4]; \
        LDSM4(bH, (u0) + (cb) + OFF_B + (boffs) + (uint32_t)p * 16 * ROWB + kb); \
        _Pragma("unroll") \
        for (int half = 0; half < 2; half++) { \
            const int nt = p * 2 + half, o = half * 2; \
            _Pragma("unroll") \
            for (int mt = 0; mt < 4; mt++) \
                MMA16816(acc[mt][nt], aH[mt], bH[o], bH[o + 1]); \
        } \
    } \
} while (0)

// ---------------- FFN1: CTA 128 thr (2 wm x 2 wn warps), tile 128x96, 2 CTAs/SM ----------------
__global__ void __launch_bounds__(128, 2)
k_ffn1(const float* __restrict__ flat,
       const float* __restrict__ w1,
       const float* __restrict__ b1) {
    const int e = blockIdx.z;
    const int n = g_cnt[e];
    const int row0 = blockIdx.x * 128;
    if (row0 >= n) return;
    const int c0 = blockIdx.y * NT;

    extern __shared__ unsigned char dsm[];
    __shared__ int s_pid[128];
    __shared__ int s_tok[128];

    const int tid  = threadIdx.x;
    const int lane = tid & 31;
    const int wrp  = tid >> 5;
    const int wm   = wrp & 1;     // 2 m-groups of 64 rows
    const int wn   = wrp >> 1;    // 2 n-groups of 48 cols

    {
        int slot = row0 + tid;
        int pid  = (slot < n) ? g_list[e * TOKENS + slot] : -1;
        s_pid[tid] = pid;
        s_tok[tid] = (pid >= 0) ? (pid >> 2) : 0;
    }
    __syncthreads();

    // staging: thread t stages full A row t; threads <96 stage full B row t
    const uint32_t soffA = (uint32_t)tid * ROWB;
    const float* myA = flat + (size_t)s_tok[tid] * HD;
    const bool do_b = (tid < NT);
    const uint32_t soffB = (uint32_t)tid * ROWB;
    const float* myB = w1 + (size_t)e * GU * HD + (size_t)(c0 + (do_b ? tid : 0)) * HD;

    const uint32_t u0 = smem_u32(dsm);
    const uint32_t aoffs = (uint32_t)(wm * 64 + (lane & 15)) * ROWB + ((lane >> 4) & 1) * 16;
    const uint32_t boffs = (uint32_t)(wn * 48 + ((lane >> 4) & 1) * 8 + (lane & 7)) * ROWB
                         + ((lane >> 3) & 1) * 16;

    float acc[4][6][4];
    #pragma unroll
    for (int mt = 0; mt < 4; mt++)
        #pragma unroll
        for (int nt = 0; nt < 6; nt++)
            #pragma unroll
            for (int q = 0; q < 4; q++) acc[mt][nt][q] = 0.f;

    // stage iter 0 into buffer 0
    stage_row_h(myA, dsm + OFF_A, soffA);
    if (do_b) stage_row_h(myB, dsm + OFF_B, soffB);
    __syncthreads();

    for (int it = 0; it < KIT; it++) {
        const uint32_t cb = (uint32_t)(it & 1) * BUFB;
        unsigned char* nb = dsm + ((it & 1) ^ 1) * BUFB;
        const bool more = (it + 1 < KIT);

        float4 pb[8];
        if (more && do_b) load_row8(myB + (it + 1) * BK, pb);   // weights: DRAM-prone, load early

        MMA_HALF(u0, cb, aoffs, boffs, acc, 0);

        float4 pa[8];
        if (more) {
            if (do_b) store_row_h(pb, nb + OFF_B, soffB);
            load_row8(myA + (it + 1) * BK, pa);                 // A: L2-hot
        }

        MMA_HALF(u0, cb, aoffs, boffs, acc, 1);

        if (more) {
            store_row_h(pa, nb + OFF_A, soffA);
            __syncthreads();
        }
    }

    // epilogue: bias + clamp + gated activation -> g_act
    const float* b1g = b1 + (size_t)e * GU + c0;
    const int i0 = c0 >> 1;
    const int l4 = lane >> 2, lm = lane & 3;
    #pragma unroll
    for (int mt = 0; mt < 4; mt++) {
        const int mA = wm * 64 + mt * 16 + l4;
        const int pid0 = s_pid[mA], pid1 = s_pid[mA + 8];
        float* a0 = g_act + (size_t)(pid0 < 0 ? 0 : pid0) * I_DIM;
        float* a1 = g_act + (size_t)(pid1 < 0 ? 0 : pid1) * I_DIM;
        #pragma unroll
        for (int nt = 0; nt < 6; nt++) {
            const int nbase = wn * 48 + nt * 8 + 2 * lm;
            float2 bb = *(const float2*)(b1g + nbase);
            const int ii = i0 + (nbase >> 1);
            {
                float gate = acc[mt][nt][0] + bb.x;
                float up   = acc[mt][nt][1] + bb.y;
                gate = fminf(gate, LIMIT);
                up   = fminf(fmaxf(up, -LIMIT), LIMIT);
                float sg = 1.f / (1.f + __expf(-ALPHA * gate));
                if (pid0 >= 0) a0[ii] = (up + 1.f) * (gate * sg);
            }
            {
                float gate = acc[mt][nt][2] + bb.x;
                float up   = acc[mt][nt][3] + bb.y;
                gate = fminf(gate, LIMIT);
                up   = fminf(fmaxf(up, -LIMIT), LIMIT);
                float sg = 1.f / (1.f + __expf(-ALPHA * gate));
                if (pid1 >= 0) a1[ii] = (up + 1.f) * (gate * sg);
            }
        }
    }
}

// ---------------- FFN2: CTA 128 thr, tile 128x96, atomic accumulate into out ----------------
__global__ void __launch_bounds__(128, 2)
k_ffn2(const float* __restrict__ w2,
       const float* __restrict__ b2,
       float* __restrict__ out) {
    const int e = blockIdx.z;
    const int n = g_cnt[e];
    const int row0 = blockIdx.x * 128;
    if (row0 >= n) return;
    const int h0 = blockIdx.y * NT;

    extern __shared__ unsigned char dsm[];
    __shared__ int s_pid[128];

    const int tid  = threadIdx.x;
    const int lane = tid & 31;
    const int wrp  = tid >> 5;
    const int wm   = wrp & 1;
    const int wn   = wrp >> 1;

    {
        int slot = row0 + tid;
        s_pid[tid] = (slot < n) ? g_list[e * TOKENS + slot] : -1;
    }
    __syncthreads();

    const uint32_t soffA = (uint32_t)tid * ROWB;
    const int apid = (s_pid[tid] < 0) ? 0 : s_pid[tid];
    const float* myA = g_act + (size_t)apid * I_DIM;
    const bool do_b = (tid < NT);
    const uint32_t soffB = (uint32_t)tid * ROWB;
    const float* myB = w2 + (size_t)e * HD * I_DIM + (size_t)(h0 + (do_b ? tid : 0)) * I_DIM;

    const uint32_t u0 = smem_u32(dsm);
    const uint32_t aoffs = (uint32_t)(wm * 64 + (lane & 15)) * ROWB + ((lane >> 4) & 1) * 16;
    const uint32_t boffs = (uint32_t)(wn * 48 + ((lane >> 4) & 1) * 8 + (lane & 7)) * ROWB
                         + ((lane >> 3) & 1) * 16;

    float acc[4][6][4];
    #pragma unroll
    for (int mt = 0; mt < 4; mt++)
        #pragma unroll
        for (int nt = 0; nt < 6; nt++)
            #pragma unroll
            for (int q = 0; q < 4; q++) acc[mt][nt][q] = 0.f;

    stage_row_h(myA, dsm + OFF_A, soffA);
    if (do_b) stage_row_h(myB, dsm + OFF_B, soffB);
    __syncthreads();

    for (int it = 0; it < KIT; it++) {
        const uint32_t cb = (uint32_t)(it & 1) * BUFB;
        unsigned char* nb = dsm + ((it & 1) ^ 1) * BUFB;
        const bool more = (it + 1 < KIT);

        float4 pb[8];
        if (more && do_b) load_row8(myB + (it + 1) * BK, pb);

        MMA_HALF(u0, cb, aoffs, boffs, acc, 0);

        float4 pa[8];
        if (more) {
            if (do_b) store_row_h(pb, nb + OFF_B, soffB);
            load_row8(myA + (it + 1) * BK, pa);
        }

        MMA_HALF(u0, cb, aoffs, boffs, acc, 1);

        if (more) {
            store_row_h(pa, nb + OFF_A, soffA);
            __syncthreads();
        }
    }

    // epilogue: out[t,h] += p * (acc + b2[e][h])  (atomic)
    const float* b2e = b2 + (size_t)e * HD;
    const int l4 = lane >> 2, lm = lane & 3;
    #pragma unroll
    for (int mt = 0; mt < 4; mt++) {
        const int mA = wm * 64 + mt * 16 + l4;
        const int pid0 = s_pid[mA], pid1 = s_pid[mA + 8];
        const float p0 = (pid0 >= 0) ? g_pp[pid0] : 0.f;
        const float p1 = (pid1 >= 0) ? g_pp[pid1] : 0.f;
        float* o0 = out + (size_t)(pid0 < 0 ? 0 : (pid0 >> 2)) * HD;
        float* o1 = out + (size_t)(pid1 < 0 ? 0 : (pid1 >> 2)) * HD;
        #pragma unroll
        for (int nt = 0; nt < 6; nt++) {
            const int ng = h0 + wn * 48 + nt * 8 + 2 * lm;
            float2 bb = *(const float2*)(b2e + ng);
            if (pid0 >= 0) {
                atomicAdd(o0 + ng,     p0 * (acc[mt][nt][0] + bb.x));
                atomicAdd(o0 + ng + 1, p0 * (acc[mt][nt][1] + bb.y));
            }
            if (pid1 >= 0) {
                atomicAdd(o1 + ng,     p1 * (acc[mt][nt][2] + bb.x));
                atomicAdd(o1 + ng + 1, p1 * (acc[mt][nt][3] + bb.y));
            }
        }
    }
}

extern "C" void kernel_launch(void* const* d_in, const int* in_sizes, int n_in,
                              void* d_out, int out_size) {
    const float* hidden = (const float*)d_in[0];
    const float* rw     = (const float*)d_in[1];
    const float* rb     = (const float*)d_in[2];
    const float* w1     = (const float*)d_in[3];
    const float* b1     = (const float*)d_in[4];
    const float* w2     = (const float*)d_in[5];
    const float* b2     = (const float*)d_in[6];
    float* out = (float*)d_out;

    cudaFuncSetAttribute(k_ffn1, cudaFuncAttributeMaxDynamicSharedMemorySize, SMEM_TOT);
    cudaFuncSetAttribute(k_ffn2, cudaFuncAttributeMaxDynamicSharedMemorySize, SMEM_TOT);

    k_init<<<1, E_NUM>>>();
    k_zero_out<<<720, 256>>>(out);
    k_router<<<TOKENS, 128>>>(hidden, rw, rb);

    dim3 g1(TOKENS / 128, GU / NT, E_NUM);   // 8 x 60 x 16
    k_ffn1<<<g1, 128, SMEM_TOT>>>(hidden, w1, b1);

    dim3 g2(TOKENS / 128, HD / NT, E_NUM);   // 8 x 30 x 16
    k_ffn2<<<g2, 128, SMEM_TOT>>>(w2, b2, out);
}

// round 15
// speedup vs baseline: 1.4202x; 1.4202x over previous
#include <cuda_runtime.h>
#include <cuda_fp16.h>
#include <math.h>
#include <stdint.h>

#define TOKENS 1024
#define HD 2880
#define E_NUM 16
#define I_DIM 2880
#define GU (2*I_DIM)
#define TOPK 4
#define NPAIR (TOKENS*TOPK)
#define ALPHA 1.702f
#define LIMIT 7.0f
#define BK 32                    // fp32 K elems per stage
#define KIT 90                   // HD/BK == I_DIM/BK
#define ROWB 80                  // smem row pitch: 64B data + 16B pad (conflict-free ldmatrix)
#define NT 192                   // CTA N-tile: divides 5760 (30) and 2880 (15) exactly

#define REG_A (128 * ROWB)       // 10240  (A: 128 rows x 32 fp16)
#define REG_B (NT * ROWB)        // 15360  (B: 192 rows x 32 fp16)
#define OFF_A 0
#define OFF_B REG_A
#define BUFB (REG_A + REG_B)     // 25600
#define NSTAGE 3
#define SMEM_TOT (NSTAGE * BUFB) // 76800

// ---------------- scratch ----------------
__device__ float g_act[NPAIR * I_DIM];
__device__ int   g_cnt[E_NUM];
__device__ int   g_list[E_NUM * TOKENS];
__device__ int   g_pe[NPAIR];
__device__ float g_pp[NPAIR];

// ---------------- helpers ----------------
__device__ __forceinline__ uint32_t smem_u32(const void* p) {
    uint32_t a;
    asm("{ .reg .u64 t; cvta.to.shared.u64 t, %1; cvt.u32.u64 %0, t; }" : "=r"(a) : "l"(p));
    return a;
}
#define LDSM4(r, addr) \
    asm volatile("ldmatrix.sync.aligned.m8n8.x4.shared.b16 {%0,%1,%2,%3}, [%4];" \
        : "=r"((r)[0]), "=r"((r)[1]), "=r"((r)[2]), "=r"((r)[3]) : "r"(addr))
#define MMA16816(d, a, b0, b1) \
    asm volatile("mma.sync.aligned.m16n8k16.row.col.f32.f16.f16.f32 " \
        "{%0,%1,%2,%3}, {%4,%5,%6,%7}, {%8,%9}, {%0,%1,%2,%3};" \
        : "+f"((d)[0]), "+f"((d)[1]), "+f"((d)[2]), "+f"((d)[3]) \
        : "r"((a)[0]), "r"((a)[1]), "r"((a)[2]), "r"((a)[3]), "r"(b0), "r"(b1))

// convert 4 float4 (16 fp32) -> 16 fp16 (32B) and store at byte offset off
__device__ __forceinline__ void store_h(const float4* v, unsigned char* sm, uint32_t off) {
    uint32_t w[8];
    #pragma unroll
    for (int q = 0; q < 4; q++) {
        __half2 h0 = __floats2half2_rn(v[q].x, v[q].y);
        __half2 h1 = __floats2half2_rn(v[q].z, v[q].w);
        w[2 * q]     = *(uint32_t*)&h0;
        w[2 * q + 1] = *(uint32_t*)&h1;
    }
    *(uint4*)(sm + off)      = make_uint4(w[0], w[1], w[2], w[3]);
    *(uint4*)(sm + off + 16) = make_uint4(w[4], w[5], w[6], w[7]);
}
__device__ __forceinline__ void stage16h(const float* __restrict__ src,
                                         unsigned char* sm, uint32_t off) {
    float4 v[4];
    const float4* s4 = (const float4*)src;
    #pragma unroll
    for (int q = 0; q < 4; q++) v[q] = s4[q];
    store_h(v, sm, off);
}

// ---------------- small kernels ----------------
__global__ void k_init() {
    if (threadIdx.x < E_NUM) g_cnt[threadIdx.x] = 0;
}

__global__ void k_zero_out(float* __restrict__ out) {
    const int total4 = TOKENS * HD / 4;
    for (int i = blockIdx.x * blockDim.x + threadIdx.x; i < total4; i += gridDim.x * blockDim.x)
        ((float4*)out)[i] = make_float4(0.f, 0.f, 0.f, 0.f);
}

__global__ void k_router(const float* __restrict__ flat,
                         const float* __restrict__ rw,
                         const float* __restrict__ rb) {
    int t = blockIdx.x, tid = threadIdx.x;
    const float* x = flat + (size_t)t * HD;
    float part[E_NUM];
    #pragma unroll
    for (int e = 0; e < E_NUM; e++) part[e] = 0.f;
    for (int h = tid; h < HD; h += 128) {
        float xv = x[h];
        #pragma unroll
        for (int e = 0; e < E_NUM; e++) part[e] += xv * rw[e * HD + h];
    }
    __shared__ float sm[E_NUM][128];
    #pragma unroll
    for (int e = 0; e < E_NUM; e++) sm[e][tid] = part[e];
    __syncthreads();
    if (tid < E_NUM) {
        float s = 0.f;
        for (int j = 0; j < 128; j++) s += sm[tid][j];
        sm[tid][0] = s + rb[tid];
    }
    __syncthreads();
    if (tid == 0) {
        float v[E_NUM];
        #pragma unroll
        for (int e = 0; e < E_NUM; e++) v[e] = sm[e][0];
        int idx[TOPK]; float val[TOPK];
        #pragma unroll
        for (int k = 0; k < TOPK; k++) {
            int bi = 0; float bv = -1e30f;
            #pragma unroll
            for (int e = 0; e < E_NUM; e++)
                if (v[e] > bv) { bv = v[e]; bi = e; }
            idx[k] = bi; val[k] = bv; v[bi] = -1e30f;
        }
        float m = val[0], s = 0.f, p[TOPK];
        #pragma unroll
        for (int k = 0; k < TOPK; k++) { p[k] = __expf(val[k] - m); s += p[k]; }
        float inv = 1.f / s;
        #pragma unroll
        for (int k = 0; k < TOPK; k++) {
            int pid = t * TOPK + k;
            g_pe[pid] = idx[k];
            g_pp[pid] = p[k] * inv;
            int slot = atomicAdd(&g_cnt[idx[k]], 1);
            g_list[idx[k] * TOKENS + slot] = pid;
        }
    }
}

// Half MMA body: one ks slice. Warp tile 64x48: mt=4 (16-row), p=3 (16-col), nt=p*2+half.
#define MMA_HALF(u0, cb, aoffs, boffs, acc, ks) do { \
    const uint32_t kb = (uint32_t)(ks) * 32u; \
    uint32_t aH[4][4]; \
    _Pragma("unroll") \
    for (int mt = 0; mt < 4; mt++) \
        LDSM4(aH[mt], (u0) + (cb) + OFF_A + (aoffs) + (uint32_t)mt * 16 * ROWB + kb); \
    _Pragma("unroll") \
    for (int p = 0; p < 3; p++) { \
        uint32_t bH[4]; \
        LDSM4(bH, (u0) + (cb) + OFF_B + (boffs) + (uint32_t)p * 16 * ROWB + kb); \
        _Pragma("unroll") \
        for (int half = 0; half < 2; half++) { \
            const int nt = p * 2 + half, o = half * 2; \
            _Pragma("unroll") \
            for (int mt = 0; mt < 4; mt++) \
                MMA16816(acc[mt][nt], aH[mt], bH[o], bH[o + 1]); \
        } \
    } \
} while (0)

// ---------------- FFN1: CTA 128x192, 8 warps (2 wm x 4 wn), warp 64x48, 3-stage pipe ----------------
__global__ void __launch_bounds__(256, 1)
k_ffn1(const float* __restrict__ flat,
       const float* __restrict__ w1,
       const float* __restrict__ b1) {
    const int e = blockIdx.z;
    const int n = g_cnt[e];
    const int row0 = blockIdx.x * 128;
    if (row0 >= n) return;
    const int c0 = blockIdx.y * NT;

    extern __shared__ unsigned char dsm[];
    __shared__ int s_pid[128];
    __shared__ int s_tok[128];

    const int tid  = threadIdx.x;
    const int lane = tid & 31;
    const int wrp  = tid >> 5;
    const int wm   = wrp & 1;     // 2 m-groups of 64 rows
    const int wn   = wrp >> 1;    // 4 n-groups of 48 cols

    if (tid < 128) {
        int slot = row0 + tid;
        int pid  = (slot < n) ? g_list[e * TOKENS + slot] : -1;
        s_pid[tid] = pid;
        s_tok[tid] = (pid >= 0) ? (pid >> 2) : 0;
    }
    __syncthreads();

    // A staging: thread -> (row tid>>1, seg tid&1); B: slices tid and 256+tid (tid<128)
    const int arow = tid >> 1, aseg = tid & 1;
    const uint32_t soffA = (uint32_t)arow * ROWB + (uint32_t)aseg * 32;
    const float* myA = flat + (size_t)s_tok[arow] * HD + aseg * 16;
    const int brow0 = tid >> 1, bseg0 = tid & 1;
    const int brow1 = (256 + tid) >> 1, bseg1 = tid & 1;
    const uint32_t soffB0 = (uint32_t)brow0 * ROWB + (uint32_t)bseg0 * 32;
    const uint32_t soffB1 = (uint32_t)brow1 * ROWB + (uint32_t)bseg1 * 32;
    const float* w1e = w1 + (size_t)e * GU * HD;
    const float* myB0 = w1e + (size_t)(c0 + brow0) * HD + bseg0 * 16;
    const float* myB1 = w1e + (size_t)(c0 + brow1) * HD + bseg1 * 16;
    const bool do_b1 = (tid < 128);

    const uint32_t u0 = smem_u32(dsm);
    const uint32_t aoffs = (uint32_t)(wm * 64 + (lane & 15)) * ROWB + ((lane >> 4) & 1) * 16;
    const uint32_t boffs = (uint32_t)(wn * 48 + ((lane >> 4) & 1) * 8 + (lane & 7)) * ROWB
                         + ((lane >> 3) & 1) * 16;

    float acc[4][6][4];
    #pragma unroll
    for (int mt = 0; mt < 4; mt++)
        #pragma unroll
        for (int nt = 0; nt < 6; nt++)
            #pragma unroll
            for (int q = 0; q < 4; q++) acc[mt][nt][q] = 0.f;

    // stage iters 0,1 into buffers 0,1
    #pragma unroll
    for (int s = 0; s < 2; s++) {
        unsigned char* bb = dsm + s * BUFB;
        stage16h(myA + s * BK, bb + OFF_A, soffA);
        stage16h(myB0 + s * BK, bb + OFF_B, soffB0);
        if (do_b1) stage16h(myB1 + s * BK, bb + OFF_B, soffB1);
    }
    __syncthreads();

    int cur = 0;
    for (int it = 0; it < KIT; it++) {
        const uint32_t cb = (uint32_t)cur * BUFB;
        int nxt = cur + 2; if (nxt >= NSTAGE) nxt -= NSTAGE;
        unsigned char* nb = dsm + nxt * BUFB;
        const bool more = (it + 2 < KIT);

        float4 pa[4], pb0[4], pb1[4];
        if (more) {
            const float4* a4 = (const float4*)(myA + (it + 2) * BK);
            const float4* b4 = (const float4*)(myB0 + (it + 2) * BK);
            #pragma unroll
            for (int q = 0; q < 4; q++) { pa[q] = a4[q]; pb0[q] = b4[q]; }
            if (do_b1) {
                const float4* c4 = (const float4*)(myB1 + (it + 2) * BK);
                #pragma unroll
                for (int q = 0; q < 4; q++) pb1[q] = c4[q];
            }
        }

        MMA_HALF(u0, cb, aoffs, boffs, acc, 0);
        if (more) store_h(pa, nb + OFF_A, soffA);
        MMA_HALF(u0, cb, aoffs, boffs, acc, 1);
        if (more) {
            store_h(pb0, nb + OFF_B, soffB0);
            if (do_b1) store_h(pb1, nb + OFF_B, soffB1);
        }
        if (it + 1 < KIT) __syncthreads();
        if (++cur >= NSTAGE) cur = 0;
    }

    // epilogue: bias + clamp + gated activation -> g_act
    const float* b1g = b1 + (size_t)e * GU + c0;
    const int i0 = c0 >> 1;
    const int l4 = lane >> 2, lm = lane & 3;
    #pragma unroll
    for (int mt = 0; mt < 4; mt++) {
        const int mA = wm * 64 + mt * 16 + l4;
        const int pid0 = s_pid[mA], pid1 = s_pid[mA + 8];
        float* a0 = g_act + (size_t)(pid0 < 0 ? 0 : pid0) * I_DIM;
        float* a1 = g_act + (size_t)(pid1 < 0 ? 0 : pid1) * I_DIM;
        #pragma unroll
        for (int nt = 0; nt < 6; nt++) {
            const int nbase = wn * 48 + nt * 8 + 2 * lm;
            float2 bb = *(const float2*)(b1g + nbase);
            const int ii = i0 + (nbase >> 1);
            {
                float gate = acc[mt][nt][0] + bb.x;
                float up   = acc[mt][nt][1] + bb.y;
                gate = fminf(gate, LIMIT);
                up   = fminf(fmaxf(up, -LIMIT), LIMIT);
                float sg = 1.f / (1.f + __expf(-ALPHA * gate));
                if (pid0 >= 0) a0[ii] = (up + 1.f) * (gate * sg);
            }
            {
                float gate = acc[mt][nt][2] + bb.x;
                float up   = acc[mt][nt][3] + bb.y;
                gate = fminf(gate, LIMIT);
                up   = fminf(fmaxf(up, -LIMIT), LIMIT);
                float sg = 1.f / (1.f + __expf(-ALPHA * gate));
                if (pid1 >= 0) a1[ii] = (up + 1.f) * (gate * sg);
            }
        }
    }
}

// ---------------- FFN2: CTA 128x192, 3-stage pipe, atomic accumulate into out ----------------
__global__ void __launch_bounds__(256, 1)
k_ffn2(const float* __restrict__ w2,
       const float* __restrict__ b2,
       float* __restrict__ out) {
    const int e = blockIdx.z;
    const int n = g_cnt[e];
    const int row0 = blockIdx.x * 128;
    if (row0 >= n) return;
    const int h0 = blockIdx.y * NT;

    extern __shared__ unsigned char dsm[];
    __shared__ int s_pid[128];

    const int tid  = threadIdx.x;
    const int lane = tid & 31;
    const int wrp  = tid >> 5;
    const int wm   = wrp & 1;
    const int wn   = wrp >> 1;

    if (tid < 128) {
        int slot = row0 + tid;
        s_pid[tid] = (slot < n) ? g_list[e * TOKENS + slot] : -1;
    }
    __syncthreads();

    const int arow = tid >> 1, aseg = tid & 1;
    const uint32_t soffA = (uint32_t)arow * ROWB + (uint32_t)aseg * 32;
    const int apid = (s_pid[arow] < 0) ? 0 : s_pid[arow];
    const float* myA = g_act + (size_t)apid * I_DIM + aseg * 16;

    const int brow0 = tid >> 1, bseg0 = tid & 1;
    const int brow1 = (256 + tid) >> 1, bseg1 = tid & 1;
    const uint32_t soffB0 = (uint32_t)brow0 * ROWB + (uint32_t)bseg0 * 32;
    const uint32_t soffB1 = (uint32_t)brow1 * ROWB + (uint32_t)bseg1 * 32;
    const float* w2e = w2 + (size_t)e * HD * I_DIM;
    const float* myB0 = w2e + (size_t)(h0 + brow0) * I_DIM + bseg0 * 16;
    const float* myB1 = w2e + (size_t)(h0 + brow1) * I_DIM + bseg1 * 16;
    const bool do_b1 = (tid < 128);

    const uint32_t u0 = smem_u32(dsm);
    const uint32_t aoffs = (uint32_t)(wm * 64 + (lane & 15)) * ROWB + ((lane >> 4) & 1) * 16;
    const uint32_t boffs = (uint32_t)(wn * 48 + ((lane >> 4) & 1) * 8 + (lane & 7)) * ROWB
                         + ((lane >> 3) & 1) * 16;

    float acc[4][6][4];
    #pragma unroll
    for (int mt = 0; mt < 4; mt++)
        #pragma unroll
        for (int nt = 0; nt < 6; nt++)
            #pragma unroll
            for (int q = 0; q < 4; q++) acc[mt][nt][q] = 0.f;

    #pragma unroll
    for (int s = 0; s < 2; s++) {
        unsigned char* bb = dsm + s * BUFB;
        stage16h(myA + s * BK, bb + OFF_A, soffA);
        stage16h(myB0 + s * BK, bb + OFF_B, soffB0);
        if (do_b1) stage16h(myB1 + s * BK, bb + OFF_B, soffB1);
    }
    __syncthreads();

    int cur = 0;
    for (int it = 0; it < KIT; it++) {
        const uint32_t cb = (uint32_t)cur * BUFB;
        int nxt = cur + 2; if (nxt >= NSTAGE) nxt -= NSTAGE;
        unsigned char* nb = dsm + nxt * BUFB;
        const bool more = (it + 2 < KIT);

        float4 pa[4], pb0[4], pb1[4];
        if (more) {
            const float4* a4 = (const float4*)(myA + (it + 2) * BK);
            const float4* b4 = (const float4*)(myB0 + (it + 2) * BK);
            #pragma unroll
            for (int q = 0; q < 4; q++) { pa[q] = a4[q]; pb0[q] = b4[q]; }
            if (do_b1) {
                const float4* c4 = (const float4*)(myB1 + (it + 2) * BK);
                #pragma unroll
                for (int q = 0; q < 4; q++) pb1[q] = c4[q];
            }
        }

        MMA_HALF(u0, cb, aoffs, boffs, acc, 0);
        if (more) store_h(pa, nb + OFF_A, soffA);
        MMA_HALF(u0, cb, aoffs, boffs, acc, 1);
        if (more) {
            store_h(pb0, nb + OFF_B, soffB0);
            if (do_b1) store_h(pb1, nb + OFF_B, soffB1);
        }
        if (it + 1 < KIT) __syncthreads();
        if (++cur >= NSTAGE) cur = 0;
    }

    // epilogue: out[t,h] += p * (acc + b2[e][h])  (atomic)
    const float* b2e = b2 + (size_t)e * HD;
    const int l4 = lane >> 2, lm = lane & 3;
    #pragma unroll
    for (int mt = 0; mt < 4; mt++) {
        const int mA = wm * 64 + mt * 16 + l4;
        const int pid0 = s_pid[mA], pid1 = s_pid[mA + 8];
        const float p0 = (pid0 >= 0) ? g_pp[pid0] : 0.f;
        const float p1 = (pid1 >= 0) ? g_pp[pid1] : 0.f;
        float* o0 = out + (size_t)(pid0 < 0 ? 0 : (pid0 >> 2)) * HD;
        float* o1 = out + (size_t)(pid1 < 0 ? 0 : (pid1 >> 2)) * HD;
        #pragma unroll
        for (int nt = 0; nt < 6; nt++) {
            const int ng = h0 + wn * 48 + nt * 8 + 2 * lm;
            float2 bb = *(const float2*)(b2e + ng);
            if (pid0 >= 0) {
                atomicAdd(o0 + ng,     p0 * (acc[mt][nt][0] + bb.x));
                atomicAdd(o0 + ng + 1, p0 * (acc[mt][nt][1] + bb.y));
            }
            if (pid1 >= 0) {
                atomicAdd(o1 + ng,     p1 * (acc[mt][nt][2] + bb.x));
                atomicAdd(o1 + ng + 1, p1 * (acc[mt][nt][3] + bb.y));
            }
        }
    }
}

extern "C" void kernel_launch(void* const* d_in, const int* in_sizes, int n_in,
                              void* d_out, int out_size) {
    const float* hidden = (const float*)d_in[0];
    const float* rw     = (const float*)d_in[1];
    const float* rb     = (const float*)d_in[2];
    const float* w1     = (const float*)d_in[3];
    const float* b1     = (const float*)d_in[4];
    const float* w2     = (const float*)d_in[5];
    const float* b2     = (const float*)d_in[6];
    float* out = (float*)d_out;

    cudaFuncSetAttribute(k_ffn1, cudaFuncAttributeMaxDynamicSharedMemorySize, SMEM_TOT);
    cudaFuncSetAttribute(k_ffn2, cudaFuncAttributeMaxDynamicSharedMemorySize, SMEM_TOT);

    k_init<<<1, E_NUM>>>();
    k_zero_out<<<720, 256>>>(out);
    k_router<<<TOKENS, 128>>>(hidden, rw, rb);

    dim3 g1(TOKENS / 128, GU / NT, E_NUM);   // 8 x 30 x 16
    k_ffn1<<<g1, 256, SMEM_TOT>>>(hidden, w1, b1);

    dim3 g2(TOKENS / 128, HD / NT, E_NUM);   // 8 x 15 x 16
    k_ffn2<<<g2, 256, SMEM_TOT>>>(w2, b2, out);
}

// round 16
// speedup vs baseline: 1.6669x; 1.1737x over previous
#include <cuda_runtime.h>
#include <cuda_fp16.h>
#include <math.h>
#include <stdint.h>

#define TOKENS 1024
#define HD 2880
#define E_NUM 16
#define I_DIM 2880
#define GU (2*I_DIM)
#define TOPK 4
#define NPAIR (TOKENS*TOPK)
#define ALPHA 1.702f
#define LIMIT 7.0f
#define BK 32                    // fp32 K elems per stage
#define KIT 90                   // HD/BK == I_DIM/BK
#define ROWB 80                  // smem row pitch: 64B data + 16B pad (conflict-free ldmatrix)
#define NT 192                   // CTA N-tile: divides 5760 (30) and 2880 (15) exactly

#define REG_A (128 * ROWB)       // 10240  (A: 128 rows x 32 fp16)
#define REG_B (NT * ROWB)        // 15360  (B: 192 rows x 32 fp16)
#define OFF_A 0
#define OFF_B REG_A
#define BUFB (REG_A + REG_B)     // 25600
#define NSTAGE 4
#define SMEM_TOT (NSTAGE * BUFB) // 102400

#define NTHREADS 384             // 8 consumer warps + 4 producer warps
// named barrier ids: FULL(s)=1+s, FREE(s)=5+s  (avoid id 0 = __syncthreads)
#define BAR_FULL(s) (1 + (s))
#define BAR_FREE(s) (5 + (s))
#define BAR_SYNC(id)   asm volatile("bar.sync %0, %1;"   :: "r"(id), "r"(NTHREADS) : "memory")
#define BAR_ARRIVE(id) asm volatile("bar.arrive %0, %1;" :: "r"(id), "r"(NTHREADS) : "memory")

// ---------------- scratch ----------------
__device__ float g_act[NPAIR * I_DIM];
__device__ int   g_cnt[E_NUM];
__device__ int   g_list[E_NUM * TOKENS];
__device__ int   g_pe[NPAIR];
__device__ float g_pp[NPAIR];

// ---------------- helpers ----------------
__device__ __forceinline__ uint32_t smem_u32(const void* p) {
    uint32_t a;
    asm("{ .reg .u64 t; cvta.to.shared.u64 t, %1; cvt.u32.u64 %0, t; }" : "=r"(a) : "l"(p));
    return a;
}
#define LDSM4(r, addr) \
    asm volatile("ldmatrix.sync.aligned.m8n8.x4.shared.b16 {%0,%1,%2,%3}, [%4];" \
        : "=r"((r)[0]), "=r"((r)[1]), "=r"((r)[2]), "=r"((r)[3]) : "r"(addr))
#define MMA16816(d, a, b0, b1) \
    asm volatile("mma.sync.aligned.m16n8k16.row.col.f32.f16.f16.f32 " \
        "{%0,%1,%2,%3}, {%4,%5,%6,%7}, {%8,%9}, {%0,%1,%2,%3};" \
        : "+f"((d)[0]), "+f"((d)[1]), "+f"((d)[2]), "+f"((d)[3]) \
        : "r"((a)[0]), "r"((a)[1]), "r"((a)[2]), "r"((a)[3]), "r"(b0), "r"(b1))

// convert 4 float4 (16 fp32) -> 16 fp16 (32B) and store at byte offset off
__device__ __forceinline__ void store_h(const float4* v, unsigned char* sm, uint32_t off) {
    uint32_t w[8];
    #pragma unroll
    for (int q = 0; q < 4; q++) {
        __half2 h0 = __floats2half2_rn(v[q].x, v[q].y);
        __half2 h1 = __floats2half2_rn(v[q].z, v[q].w);
        w[2 * q]     = *(uint32_t*)&h0;
        w[2 * q + 1] = *(uint32_t*)&h1;
    }
    *(uint4*)(sm + off)      = make_uint4(w[0], w[1], w[2], w[3]);
    *(uint4*)(sm + off + 16) = make_uint4(w[4], w[5], w[6], w[7]);
}

// ---------------- small kernels ----------------
__global__ void k_init() {
    if (threadIdx.x < E_NUM) g_cnt[threadIdx.x] = 0;
}

__global__ void k_zero_out(float* __restrict__ out) {
    const int total4 = TOKENS * HD / 4;
    for (int i = blockIdx.x * blockDim.x + threadIdx.x; i < total4; i += gridDim.x * blockDim.x)
        ((float4*)out)[i] = make_float4(0.f, 0.f, 0.f, 0.f);
}

__global__ void k_router(const float* __restrict__ flat,
                         const float* __restrict__ rw,
                         const float* __restrict__ rb) {
    int t = blockIdx.x, tid = threadIdx.x;
    const float* x = flat + (size_t)t * HD;
    float part[E_NUM];
    #pragma unroll
    for (int e = 0; e < E_NUM; e++) part[e] = 0.f;
    for (int h = tid; h < HD; h += 128) {
        float xv = x[h];
        #pragma unroll
        for (int e = 0; e < E_NUM; e++) part[e] += xv * rw[e * HD + h];
    }
    __shared__ float sm[E_NUM][128];
    #pragma unroll
    for (int e = 0; e < E_NUM; e++) sm[e][tid] = part[e];
    __syncthreads();
    if (tid < E_NUM) {
        float s = 0.f;
        for (int j = 0; j < 128; j++) s += sm[tid][j];
        sm[tid][0] = s + rb[tid];
    }
    __syncthreads();
    if (tid == 0) {
        float v[E_NUM];
        #pragma unroll
        for (int e = 0; e < E_NUM; e++) v[e] = sm[e][0];
        int idx[TOPK]; float val[TOPK];
        #pragma unroll
        for (int k = 0; k < TOPK; k++) {
            int bi = 0; float bv = -1e30f;
            #pragma unroll
            for (int e = 0; e < E_NUM; e++)
                if (v[e] > bv) { bv = v[e]; bi = e; }
            idx[k] = bi; val[k] = bv; v[bi] = -1e30f;
        }
        float m = val[0], s = 0.f, p[TOPK];
        #pragma unroll
        for (int k = 0; k < TOPK; k++) { p[k] = __expf(val[k] - m); s += p[k]; }
        float inv = 1.f / s;
        #pragma unroll
        for (int k = 0; k < TOPK; k++) {
            int pid = t * TOPK + k;
            g_pe[pid] = idx[k];
            g_pp[pid] = p[k] * inv;
            int slot = atomicAdd(&g_cnt[idx[k]], 1);
            g_list[idx[k] * TOKENS + slot] = pid;
        }
    }
}

// Half MMA body: one ks slice. Warp tile 64x48: mt=4 (16-row), p=3 (16-col), nt=p*2+half.
#define MMA_HALF(u0, cb, aoffs, boffs, acc, ks) do { \
    const uint32_t kb = (uint32_t)(ks) * 32u; \
    uint32_t aH[4][4]; \
    _Pragma("unroll") \
    for (int mt = 0; mt < 4; mt++) \
        LDSM4(aH[mt], (u0) + (cb) + OFF_A + (aoffs) + (uint32_t)mt * 16 * ROWB + kb); \
    _Pragma("unroll") \
    for (int p = 0; p < 3; p++) { \
        uint32_t bH[4]; \
        LDSM4(bH, (u0) + (cb) + OFF_B + (boffs) + (uint32_t)p * 16 * ROWB + kb); \
        _Pragma("unroll") \
        for (int half = 0; half < 2; half++) { \
            const int nt = p * 2 + half, o = half * 2; \
            _Pragma("unroll") \
            for (int mt = 0; mt < 4; mt++) \
                MMA16816(acc[mt][nt], aH[mt], bH[o], bH[o + 1]); \
        } \
    } \
} while (0)

// Producer loop: 128 producer threads stage A(128 rows) + B(NT rows), 5 half-slices each.
#define PRODUCER_LOOP(aBase, bBase, aStride, bStride) do { \
    const int p = tid - 256; \
    const float* srcs[5]; \
    uint32_t doffs[5]; \
    _Pragma("unroll") \
    for (int k = 0; k < 5; k++) { \
        int gs = p + k * 128; \
        if (gs < 256) { \
            int row = gs >> 1, seg = gs & 1; \
            srcs[k] = (aBase) + (size_t)row * 0 + (size_t)(aStride[row]) + seg * 16; \
            doffs[k] = OFF_A + (uint32_t)row * ROWB + (uint32_t)seg * 32; \
        } else { \
            int b = gs - 256, row = b >> 1, seg = b & 1; \
            srcs[k] = (bBase) + (size_t)row * (bStride) + seg * 16; \
            doffs[k] = OFF_B + (uint32_t)row * ROWB + (uint32_t)seg * 32; \
        } \
    } \
    for (int it = 0; it < KIT; it++) { \
        const int s = it & 3; \
        if (it >= NSTAGE) BAR_SYNC(BAR_FREE(s)); \
        unsigned char* nb = dsm + s * BUFB; \
        float4 v[5][4]; \
        _Pragma("unroll") \
        for (int k = 0; k < 5; k++) { \
            const float4* s4 = (const float4*)(srcs[k] + it * BK); \
            _Pragma("unroll") \
            for (int q = 0; q < 4; q++) v[k][q] = s4[q]; \
        } \
        _Pragma("unroll") \
        for (int k = 0; k < 5; k++) store_h(v[k], nb, doffs[k]); \
        BAR_ARRIVE(BAR_FULL(s)); \
    } \
} while (0)

// ---------------- FFN1: 384 thr = 8 consumer warps (2x4, warp 64x48) + 4 producer warps ----------------
__global__ void __launch_bounds__(NTHREADS, 1)
k_ffn1(const float* __restrict__ flat,
       const float* __restrict__ w1,
       const float* __restrict__ b1) {
    const int e = blockIdx.z;
    const int n = g_cnt[e];
    const int row0 = blockIdx.x * 128;
    if (row0 >= n) return;
    const int c0 = blockIdx.y * NT;

    extern __shared__ unsigned char dsm[];
    __shared__ int s_pid[128];
    __shared__ size_t s_aoff[128];   // per-row byte... element offset of A row in flat

    const int tid  = threadIdx.x;
    const int lane = tid & 31;
    const int wrp  = tid >> 5;

    if (tid < 128) {
        int slot = row0 + tid;
        int pid  = (slot < n) ? g_list[e * TOKENS + slot] : -1;
        s_pid[tid] = pid;
        s_aoff[tid] = (size_t)((pid >= 0) ? (pid >> 2) : 0) * HD;
    }
    __syncthreads();

    if (wrp >= 8) {
        // -------- producer --------
        const float* w1e = w1 + (size_t)e * GU * HD + (size_t)c0 * HD;
        const int p = tid - 256;
        const float* srcs[5];
        uint32_t doffs[5];
        #pragma unroll
        for (int k = 0; k < 5; k++) {
            int gs = p + k * 128;
            if (gs < 256) {
                int row = gs >> 1, seg = gs & 1;
                srcs[k] = flat + s_aoff[row] + seg * 16;
                doffs[k] = OFF_A + (uint32_t)row * ROWB + (uint32_t)seg * 32;
            } else {
                int b = gs - 256, row = b >> 1, seg = b & 1;
                srcs[k] = w1e + (size_t)row * HD + seg * 16;
                doffs[k] = OFF_B + (uint32_t)row * ROWB + (uint32_t)seg * 32;
            }
        }
        for (int it = 0; it < KIT; it++) {
            const int s = it & 3;
            if (it >= NSTAGE) BAR_SYNC(BAR_FREE(s));
            unsigned char* nb = dsm + s * BUFB;
            float4 v[5][4];
            #pragma unroll
            for (int k = 0; k < 5; k++) {
                const float4* s4 = (const float4*)(srcs[k] + it * BK);
                #pragma unroll
                for (int q = 0; q < 4; q++) v[k][q] = s4[q];
            }
            #pragma unroll
            for (int k = 0; k < 5; k++) store_h(v[k], nb, doffs[k]);
            BAR_ARRIVE(BAR_FULL(s));
        }
        return;
    }

    // -------- consumer --------
    const int wm = wrp & 1;     // 2 m-groups of 64 rows
    const int wn = wrp >> 1;    // 4 n-groups of 48 cols
    const uint32_t u0 = smem_u32(dsm);
    const uint32_t aoffs = (uint32_t)(wm * 64 + (lane & 15)) * ROWB + ((lane >> 4) & 1) * 16;
    const uint32_t boffs = (uint32_t)(wn * 48 + ((lane >> 4) & 1) * 8 + (lane & 7)) * ROWB
                         + ((lane >> 3) & 1) * 16;

    float acc[4][6][4];
    #pragma unroll
    for (int mt = 0; mt < 4; mt++)
        #pragma unroll
        for (int nt = 0; nt < 6; nt++)
            #pragma unroll
            for (int q = 0; q < 4; q++) acc[mt][nt][q] = 0.f;

    for (int i = 0; i < KIT; i++) {
        const int s = i & 3;
        const uint32_t cb = (uint32_t)s * BUFB;
        BAR_SYNC(BAR_FULL(s));
        MMA_HALF(u0, cb, aoffs, boffs, acc, 0);
        MMA_HALF(u0, cb, aoffs, boffs, acc, 1);
        BAR_ARRIVE(BAR_FREE(s));
    }

    // epilogue: bias + clamp + gated activation -> g_act
    const float* b1g = b1 + (size_t)e * GU + c0;
    const int i0 = c0 >> 1;
    const int l4 = lane >> 2, lm = lane & 3;
    #pragma unroll
    for (int mt = 0; mt < 4; mt++) {
        const int mA = wm * 64 + mt * 16 + l4;
        const int pid0 = s_pid[mA], pid1 = s_pid[mA + 8];
        float* a0 = g_act + (size_t)(pid0 < 0 ? 0 : pid0) * I_DIM;
        float* a1 = g_act + (size_t)(pid1 < 0 ? 0 : pid1) * I_DIM;
        #pragma unroll
        for (int nt = 0; nt < 6; nt++) {
            const int nbase = wn * 48 + nt * 8 + 2 * lm;
            float2 bb = *(const float2*)(b1g + nbase);
            const int ii = i0 + (nbase >> 1);
            {
                float gate = acc[mt][nt][0] + bb.x;
                float up   = acc[mt][nt][1] + bb.y;
                gate = fminf(gate, LIMIT);
                up   = fminf(fmaxf(up, -LIMIT), LIMIT);
                float sg = 1.f / (1.f + __expf(-ALPHA * gate));
                if (pid0 >= 0) a0[ii] = (up + 1.f) * (gate * sg);
            }
            {
                float gate = acc[mt][nt][2] + bb.x;
                float up   = acc[mt][nt][3] + bb.y;
                gate = fminf(gate, LIMIT);
                up   = fminf(fmaxf(up, -LIMIT), LIMIT);
                float sg = 1.f / (1.f + __expf(-ALPHA * gate));
                if (pid1 >= 0) a1[ii] = (up + 1.f) * (gate * sg);
            }
        }
    }
}

// ---------------- FFN2: same specialization, atomic accumulate into out ----------------
__global__ void __launch_bounds__(NTHREADS, 1)
k_ffn2(const float* __restrict__ w2,
       const float* __restrict__ b2,
       float* __restrict__ out) {
    const int e = blockIdx.z;
    const int n = g_cnt[e];
    const int row0 = blockIdx.x * 128;
    if (row0 >= n) return;
    const int h0 = blockIdx.y * NT;

    extern __shared__ unsigned char dsm[];
    __shared__ int s_pid[128];
    __shared__ size_t s_aoff[128];

    const int tid  = threadIdx.x;
    const int lane = tid & 31;
    const int wrp  = tid >> 5;

    if (tid < 128) {
        int slot = row0 + tid;
        int pid  = (slot < n) ? g_list[e * TOKENS + slot] : -1;
        s_pid[tid] = pid;
        s_aoff[tid] = (size_t)(pid < 0 ? 0 : pid) * I_DIM;
    }
    __syncthreads();

    if (wrp >= 8) {
        // -------- producer --------
        const float* w2e = w2 + (size_t)e * HD * I_DIM + (size_t)h0 * I_DIM;
        const int p = tid - 256;
        const float* srcs[5];
        uint32_t doffs[5];
        #pragma unroll
        for (int k = 0; k < 5; k++) {
            int gs = p + k * 128;
            if (gs < 256) {
                int row = gs >> 1, seg = gs & 1;
                srcs[k] = g_act + s_aoff[row] + seg * 16;
                doffs[k] = OFF_A + (uint32_t)row * ROWB + (uint32_t)seg * 32;
            } else {
                int b = gs - 256, row = b >> 1, seg = b & 1;
                srcs[k] = w2e + (size_t)row * I_DIM + seg * 16;
                doffs[k] = OFF_B + (uint32_t)row * ROWB + (uint32_t)seg * 32;
            }
        }
        for (int it = 0; it < KIT; it++) {
            const int s = it & 3;
            if (it >= NSTAGE) BAR_SYNC(BAR_FREE(s));
            unsigned char* nb = dsm + s * BUFB;
            float4 v[5][4];
            #pragma unroll
            for (int k = 0; k < 5; k++) {
                const float4* s4 = (const float4*)(srcs[k] + it * BK);
                #pragma unroll
                for (int q = 0; q < 4; q++) v[k][q] = s4[q];
            }
            #pragma unroll
            for (int k = 0; k < 5; k++) store_h(v[k], nb, doffs[k]);
            BAR_ARRIVE(BAR_FULL(s));
        }
        return;
    }

    // -------- consumer --------
    const int wm = wrp & 1;
    const int wn = wrp >> 1;
    const uint32_t u0 = smem_u32(dsm);
    const uint32_t aoffs = (uint32_t)(wm * 64 + (lane & 15)) * ROWB + ((lane >> 4) & 1) * 16;
    const uint32_t boffs = (uint32_t)(wn * 48 + ((lane >> 4) & 1) * 8 + (lane & 7)) * ROWB
                         + ((lane >> 3) & 1) * 16;

    float acc[4][6][4];
    #pragma unroll
    for (int mt = 0; mt < 4; mt++)
        #pragma unroll
        for (int nt = 0; nt < 6; nt++)
            #pragma unroll
            for (int q = 0; q < 4; q++) acc[mt][nt][q] = 0.f;

    for (int i = 0; i < KIT; i++) {
        const int s = i & 3;
        const uint32_t cb = (uint32_t)s * BUFB;
        BAR_SYNC(BAR_FULL(s));
        MMA_HALF(u0, cb, aoffs, boffs, acc, 0);
        MMA_HALF(u0, cb, aoffs, boffs, acc, 1);
        BAR_ARRIVE(BAR_FREE(s));
    }

    // epilogue: out[t,h] += p * (acc + b2[e][h])  (atomic)
    const float* b2e = b2 + (size_t)e * HD;
    const int l4 = lane >> 2, lm = lane & 3;
    #pragma unroll
    for (int mt = 0; mt < 4; mt++) {
        const int mA = wm * 64 + mt * 16 + l4;
        const int pid0 = s_pid[mA], pid1 = s_pid[mA + 8];
        const float p0 = (pid0 >= 0) ? g_pp[pid0] : 0.f;
        const float p1 = (pid1 >= 0) ? g_pp[pid1] : 0.f;
        float* o0 = out + (size_t)(pid0 < 0 ? 0 : (pid0 >> 2)) * HD;
        float* o1 = out + (size_t)(pid1 < 0 ? 0 : (pid1 >> 2)) * HD;
        #pragma unroll
        for (int nt = 0; nt < 6; nt++) {
            const int ng = h0 + wn * 48 + nt * 8 + 2 * lm;
            float2 bb = *(const float2*)(b2e + ng);
            if (pid0 >= 0) {
                atomicAdd(o0 + ng,     p0 * (acc[mt][nt][0] + bb.x));
                atomicAdd(o0 + ng + 1, p0 * (acc[mt][nt][1] + bb.y));
            }
            if (pid1 >= 0) {
                atomicAdd(o1 + ng,     p1 * (acc[mt][nt][2] + bb.x));
                atomicAdd(o1 + ng + 1, p1 * (acc[mt][nt][3] + bb.y));
            }
        }
    }
}

extern "C" void kernel_launch(void* const* d_in, const int* in_sizes, int n_in,
                              void* d_out, int out_size) {
    const float* hidden = (const float*)d_in[0];
    const float* rw     = (const float*)d_in[1];
    const float* rb     = (const float*)d_in[2];
    const float* w1     = (const float*)d_in[3];
    const float* b1     = (const float*)d_in[4];
    const float* w2     = (const float*)d_in[5];
    const float* b2     = (const float*)d_in[6];
    float* out = (float*)d_out;

    cudaFuncSetAttribute(k_ffn1, cudaFuncAttributeMaxDynamicSharedMemorySize, SMEM_TOT);
    cudaFuncSetAttribute(k_ffn2, cudaFuncAttributeMaxDynamicSharedMemorySize, SMEM_TOT);

    k_init<<<1, E_NUM>>>();
    k_zero_out<<<720, 256>>>(out);
    k_router<<<TOKENS, 128>>>(hidden, rw, rb);

    dim3 g1(TOKENS / 128, GU / NT, E_NUM);   // 8 x 30 x 16
    k_ffn1<<<g1, NTHREADS, SMEM_TOT>>>(hidden, w1, b1);

    dim3 g2(TOKENS / 128, HD / NT, E_NUM);   // 8 x 15 x 16
    k_ffn2<<<g2, NTHREADS, SMEM_TOT>>>(w2, b2, out);
}